// round 1
// baseline (speedup 1.0000x reference)
#include <cuda_runtime.h>
#include <cuda_bf16.h>
#include <math_constants.h>

#define NEG_INF_VAL (-1.0e9f)

// Hardcoded problem constants (registry shape): P (max_num_patches) and k.
#define P_PATCHES 1024
#define TOPK 2

__device__ __forceinline__ void upd(float v, float& m1, float& m2) {
    if (v > m1) { m2 = m1; m1 = v; }
    else if (v < m1) { m2 = fmaxf(m2, v); }
    // v == m1: duplicate of the max -> reference masks it out entirely; skip.
}

__global__ void __launch_bounds__(128)
topk_mean_kernel(const float* __restrict__ h,
                 const int* __restrict__ pids,
                 float* __restrict__ out,
                 int seq, int E)
{
    const int p = blockIdx.x;          // patch id
    const int b = blockIdx.y;          // batch
    const int* pid_b = pids + (long)b * seq;

    // lower_bound(p) and lower_bound(p+1) over sorted patch_ids[b]
    int lo = 0, hi = seq;
    while (lo < hi) { int mid = (lo + hi) >> 1; if (pid_b[mid] < p) lo = mid + 1; else hi = mid; }
    const int start = lo;
    hi = seq;
    while (lo < hi) { int mid = (lo + hi) >> 1; if (pid_b[mid] < p + 1) lo = mid + 1; else hi = mid; }
    const int end = lo;
    const int count = end - start;

    const int e = threadIdx.x * 4;
    if (e >= E) return;

    float4* outv = (float4*)(out + ((long)b * P_PATCHES + p) * E + e);

    if (count == 0) { *outv = make_float4(0.f, 0.f, 0.f, 0.f); return; }

    const float* hb = h + (long)b * seq * E + e;

    float4 m1 = make_float4(-CUDART_INF_F, -CUDART_INF_F, -CUDART_INF_F, -CUDART_INF_F);
    float4 m2 = m1;

    for (int t = start; t < end; ++t) {
        float4 v = *(const float4*)(hb + (long)t * E);
        upd(v.x, m1.x, m2.x);
        upd(v.y, m1.y, m2.y);
        upd(v.z, m1.z, m2.z);
        upd(v.w, m1.w, m2.w);
    }

    float4 r;
    if (count == 1) {
        r = m1;
    } else {
        // If every token equaled the max in this dim, the reference's second
        // pass sees all NEG_INF and averages it in.
        float s2x = (m2.x == -CUDART_INF_F) ? NEG_INF_VAL : m2.x;
        float s2y = (m2.y == -CUDART_INF_F) ? NEG_INF_VAL : m2.y;
        float s2z = (m2.z == -CUDART_INF_F) ? NEG_INF_VAL : m2.z;
        float s2w = (m2.w == -CUDART_INF_F) ? NEG_INF_VAL : m2.w;
        r = make_float4((m1.x + s2x) * 0.5f, (m1.y + s2y) * 0.5f,
                        (m1.z + s2z) * 0.5f, (m1.w + s2w) * 0.5f);
    }
    *outv = r;
}

extern "C" void kernel_launch(void* const* d_in, const int* in_sizes, int n_in,
                              void* d_out, int out_size)
{
    const float* h    = (const float*)d_in[0];
    const int*   pids = (const int*)d_in[1];
    float*       out  = (float*)d_out;

    const int total_tok = in_sizes[1];           // bs * seq
    const int E  = in_sizes[0] / total_tok;      // 512
    const int bs = out_size / (P_PATCHES * E);   // 8
    const int seq = total_tok / bs;              // 4096

    dim3 grid(P_PATCHES, bs);
    dim3 block(E / 4);                           // 128 threads, 4 dims each (float4)
    topk_mean_kernel<<<grid, block>>>(h, pids, out, seq, E);
}

// round 2
// speedup vs baseline: 1.5183x; 1.5183x over previous
#include <cuda_runtime.h>
#include <cuda_bf16.h>
#include <math_constants.h>

#define NEG_INF_VAL (-1.0e9f)
#define P_PATCHES 1024
#define MAX_BS 16

// Cumulative segment starts: starts[b*(P+1)+p] = lower_bound(patch_ids[b], p).
// starts[b*(P+1)+P] = seq. Segment for patch p is [starts[p], starts[p+1]).
__device__ int g_starts[MAX_BS * (P_PATCHES + 1)];

__global__ void __launch_bounds__(P_PATCHES)
bounds_kernel(const int* __restrict__ pids, int seq)
{
    extern __shared__ int s_pid[];
    const int b = blockIdx.x;
    const int* pid_b = pids + (long)b * seq;

    for (int t = threadIdx.x; t < seq; t += blockDim.x)
        s_pid[t] = pid_b[t];
    __syncthreads();

    const int p = threadIdx.x;  // one patch per thread, exactly P threads
    int lo = 0, hi = seq;
    while (lo < hi) {
        int mid = (lo + hi) >> 1;
        if (s_pid[mid] < p) lo = mid + 1; else hi = mid;
    }
    g_starts[b * (P_PATCHES + 1) + p] = lo;
    if (p == 0) g_starts[b * (P_PATCHES + 1) + P_PATCHES] = seq;
}

__device__ __forceinline__ void upd(float v, float& m1, float& m2) {
    if (v > m1) { m2 = m1; m1 = v; }
    else if (v < m1) { m2 = fmaxf(m2, v); }
    // v == m1: duplicate of the max -> masked out entirely by the reference; skip.
}

__global__ void __launch_bounds__(128)
topk_mean_kernel(const float* __restrict__ h,
                 float* __restrict__ out,
                 int seq, int E)
{
    const int p = blockIdx.x;          // patch id
    const int b = blockIdx.y;          // batch

    const int start = g_starts[b * (P_PATCHES + 1) + p];
    const int end   = g_starts[b * (P_PATCHES + 1) + p + 1];
    const int count = end - start;

    const int e = threadIdx.x * 4;
    float4* outv = (float4*)(out + ((long)b * P_PATCHES + p) * E + e);

    if (count == 0) { *outv = make_float4(0.f, 0.f, 0.f, 0.f); return; }

    const float* hb = h + (long)b * seq * E + e;

    float4 m1 = make_float4(-CUDART_INF_F, -CUDART_INF_F, -CUDART_INF_F, -CUDART_INF_F);
    float4 m2 = m1;

    // Software-pipelined token loop: keep the next load in flight while
    // updating the running top-2 for the current token.
    float4 v = *(const float4*)(hb + (long)start * E);
    for (int t = start + 1; t < end; ++t) {
        float4 nxt = *(const float4*)(hb + (long)t * E);
        upd(v.x, m1.x, m2.x);
        upd(v.y, m1.y, m2.y);
        upd(v.z, m1.z, m2.z);
        upd(v.w, m1.w, m2.w);
        v = nxt;
    }
    upd(v.x, m1.x, m2.x);
    upd(v.y, m1.y, m2.y);
    upd(v.z, m1.z, m2.z);
    upd(v.w, m1.w, m2.w);

    float4 r;
    if (count == 1) {
        r = m1;
    } else {
        // If every token equaled the max in a dim, the reference's second pass
        // sees all NEG_INF and averages it in.
        float s2x = (m2.x == -CUDART_INF_F) ? NEG_INF_VAL : m2.x;
        float s2y = (m2.y == -CUDART_INF_F) ? NEG_INF_VAL : m2.y;
        float s2z = (m2.z == -CUDART_INF_F) ? NEG_INF_VAL : m2.z;
        float s2w = (m2.w == -CUDART_INF_F) ? NEG_INF_VAL : m2.w;
        r = make_float4((m1.x + s2x) * 0.5f, (m1.y + s2y) * 0.5f,
                        (m1.z + s2z) * 0.5f, (m1.w + s2w) * 0.5f);
    }
    *outv = r;
}

extern "C" void kernel_launch(void* const* d_in, const int* in_sizes, int n_in,
                              void* d_out, int out_size)
{
    const float* h    = (const float*)d_in[0];
    const int*   pids = (const int*)d_in[1];
    float*       out  = (float*)d_out;

    const int total_tok = in_sizes[1];           // bs * seq
    const int E  = in_sizes[0] / total_tok;      // 512
    const int bs = out_size / (P_PATCHES * E);   // 8
    const int seq = total_tok / bs;              // 4096

    bounds_kernel<<<bs, P_PATCHES, seq * sizeof(int)>>>(pids, seq);

    dim3 grid(P_PATCHES, bs);
    dim3 block(E / 4);                           // 128 threads, 4 dims (float4) each
    topk_mean_kernel<<<grid, block>>>(h, out, seq, E);
}